// round 10
// baseline (speedup 1.0000x reference)
#include <cuda_runtime.h>
#include <math.h>
#include <stdint.h>

// Problem constants
#define BB   8
#define TT   8
#define HH   14
#define WW   14
#define SPA  1568          // T*H*W
#define MTOT 12544         // B*SPA
#define KC   32            // GEMM k-chunk

// ---------------- scratch (device globals; no allocation allowed) -------------
__device__ float g_xT [(size_t)MTOT * 832];   // x channels-last
__device__ float g_xmT[(size_t)MTOT * 832];   // maxpool(x) channels-last
__device__ float g_x1a[(size_t)MTOT * 160];   // branch1 intermediate
__device__ float g_x2a[(size_t)MTOT * 32];    // branch2 intermediate
__device__ float g_samp[(size_t)MTOT * 4320]; // im2col / sampled rows (tf32 bits)
__device__ float g_conv[(size_t)MTOT * 320];  // raw conv output (max layer2)
__device__ float g_offb[(size_t)MTOT * 96];   // offset field (stride 96 for k=3)
__device__ float g_stats[1024];               // [0..511]=mean, [512..1023]=var
__device__ float g_wT  [1972224];             // transposed main-conv weights (tf32)
__device__ float g_woffT[520000];             // transposed offset-conv weights

__device__ __forceinline__ uint32_t f2tf(float x) {
    uint32_t u; asm("cvt.rna.tf32.f32 %0, %1;" : "=r"(u) : "f"(x)); return u;
}
__device__ __forceinline__ float f2tff(float x) { return __uint_as_float(f2tf(x)); }

__device__ __forceinline__ void cpa16(uint32_t dst, const void* src, int szBytes) {
    asm volatile("cp.async.cg.shared.global [%0], [%1], 16, %2;"
                 :: "r"(dst), "l"(src), "r"(szBytes));
}

// ---------------- fused prep: transpose x (channels-last) + all weight jobs ---
struct WJobs {
    const float* src[12];
    float*       dst[12];
    int cout[12], coutpad[12], cin[12], kk[12], cvt[12];
    int start[13];
};
#define NT_BLOCKS (49 * 26 * 8)   // transpose tiles: (SPA/32) * (832/32) * B

__global__ void k_prep(WJobs jb, const float* __restrict__ x, float* __restrict__ xT) {
    int bid = blockIdx.x;
    if (bid < NT_BLOCKS) {
        __shared__ float tile[32][33];
        int sx = bid % 49;
        int cy = (bid / 49) % 26;
        int b  = bid / (49 * 26);
        int s0 = sx * 32, c0 = cy * 32;
        int tx = threadIdx.x % 32, ty = threadIdx.x / 32;
        #pragma unroll
        for (int i = ty; i < 32; i += 8)
            tile[i][tx] = x[((size_t)b * 832 + (c0 + i)) * SPA + s0 + tx];
        __syncthreads();
        #pragma unroll
        for (int i = ty; i < 32; i += 8)
            xT[((size_t)b * SPA + (s0 + i)) * 832 + c0 + tx] = tile[tx][i];
    } else {
        int idx = (bid - NT_BLOCKS) * 256 + threadIdx.x;
        if (idx >= jb.start[12]) return;
        int j = 0;
        #pragma unroll
        for (int i = 1; i < 12; i++) if (idx >= jb.start[i]) j = i;
        int local = idx - jb.start[j];
        int cp = jb.coutpad[j], ci = jb.cin[j], K = jb.kk[j];
        int oc = local % cp; int rest = local / cp;
        int c  = rest % ci;  int kk = rest / ci;
        float v = (oc < jb.cout[j]) ? jb.src[j][((size_t)oc * ci + c) * K + kk] : 0.f;
        if (jb.cvt[j]) v = __uint_as_float(f2tf(v));
        jb.dst[j][local] = v;
    }
}

// ---------------- separable 3-max along one dim, channels-last ----------------
__global__ void k_max3(const float* __restrict__ in, float* __restrict__ out,
                       int ddiv, int dmod) {
    size_t idx = (size_t)blockIdx.x * blockDim.x + threadIdx.x;
    if (idx >= (size_t)MTOT * 208) return;
    int c4 = (int)(idx % 208);
    size_t m = idx / 208;
    int s = (int)(m % SPA);
    int coord = (s / ddiv) % dmod;
    const float4* p = reinterpret_cast<const float4*>(in) + m * 208 + c4;
    float4 v = *p;
    if (coord > 0) {
        float4 u = *(p - (size_t)ddiv * 208);
        v.x = fmaxf(v.x, u.x); v.y = fmaxf(v.y, u.y);
        v.z = fmaxf(v.z, u.z); v.w = fmaxf(v.w, u.w);
    }
    if (coord < dmod - 1) {
        float4 u = *(p + (size_t)ddiv * 208);
        v.x = fmaxf(v.x, u.x); v.y = fmaxf(v.y, u.y);
        v.z = fmaxf(v.z, u.z); v.w = fmaxf(v.w, u.w);
    }
    reinterpret_cast<float4*>(out)[m * 208 + c4] = v;
}

// ---------------- 3-stage pipelined tf32 GEMM (templated M-tile) --------------
// C[M,N] = A[M,K] @ B[K,N] (+bias). A,B pre-converted to tf32 bit patterns.
// MT=128: CTA 128x128, warp 64x32, for N>128. MT=64: CTA 64x128, warp 32x32,
// for N<=128 (doubles grid -> fills all SMs). 3 cp.async stages (prefetch 2).
template<int MT>
__global__ __launch_bounds__(256, 2) void k_gemm_pipe(
    const float* __restrict__ A, const float* __restrict__ Bm,
    const float* __restrict__ bias, int nBias,
    float* __restrict__ Cc, int Nn, int Kn)
{
    extern __shared__ float sm[];
    constexpr int ASTG = MT * 36;        // floats per A stage
    constexpr int BSTG = 32 * 132;       // floats per B stage
    constexpr int NMT  = MT / 32;        // m-subtiles per warp
    constexpr int TPR  = 256 / MT;       // threads per A row
    constexpr int CPT  = 32 / TPR;       // A cols per thread
    constexpr int NCPA = CPT / 4;        // cp.async per thread for A

    int tid = threadIdx.x;
    int lane = tid & 31, warp = tid >> 5;
    int warpM = warp & 1, warpN = warp >> 1;
    int m0 = blockIdx.y * MT, n0 = blockIdx.x * 128;
    int g = lane >> 2, tg = lane & 3;

    float acc[NMT][4][4];
    #pragma unroll
    for (int i = 0; i < NMT; i++)
        #pragma unroll
        for (int j = 0; j < 4; j++)
            #pragma unroll
            for (int q = 0; q < 4; q++) acc[i][j][q] = 0.f;

    const int aRowT = tid / TPR;
    const int aCol0 = (tid % TPR) * CPT;
    const float* aPtr = A + (size_t)(m0 + aRowT) * Kn + aCol0;
    const int bRowT = tid >> 3;
    const int bCol0 = (tid & 7) * 4;

    uint32_t aBase = (uint32_t)__cvta_generic_to_shared(&sm[aRowT * 36 + aCol0]);
    uint32_t bBase = (uint32_t)__cvta_generic_to_shared(&sm[3 * ASTG + bRowT * 132 + bCol0]);

    int nChunks = Kn / KC;

    auto issue = [&](int chunk) {
        int st = chunk % 3;
        const float* ap = aPtr + chunk * KC;
        #pragma unroll
        for (int j = 0; j < NCPA; j++)
            cpa16(aBase + (uint32_t)st * ASTG * 4 + j * 16, ap + j * 4, 16);
        const float* bp = Bm + (size_t)(chunk * KC + bRowT) * Nn;
        #pragma unroll
        for (int j = 0; j < 4; j++) {
            int col = bCol0 + j * 32;
            int sz = (n0 + col < Nn) ? 16 : 0;
            cpa16(bBase + (uint32_t)st * BSTG * 4 + j * 32 * 4, bp + n0 + col, sz);
        }
        asm volatile("cp.async.commit_group;");
    };

    issue(0);
    if (nChunks > 1) issue(1);

    for (int c = 0; c < nChunks; c++) {
        int st = c % 3;
        if (c + 2 < nChunks) {
            issue(c + 2);
            asm volatile("cp.async.wait_group 2;");
        } else if (c + 1 < nChunks) {
            asm volatile("cp.async.wait_group 1;");
        } else {
            asm volatile("cp.async.wait_group 0;");
        }
        __syncthreads();

        const float* As = sm + (size_t)st * ASTG;
        const float* Bs = sm + 3 * ASTG + (size_t)st * BSTG;
        #pragma unroll
        for (int ks = 0; ks < 4; ks++) {
            uint32_t af[NMT][4], bf[4][2];
            #pragma unroll
            for (int mt = 0; mt < NMT; mt++) {
                int mr = warpM * (MT / 2) + mt * 16 + g;
                af[mt][0] = __float_as_uint(As[mr * 36       + ks * 8 + tg]);
                af[mt][1] = __float_as_uint(As[(mr + 8) * 36 + ks * 8 + tg]);
                af[mt][2] = __float_as_uint(As[mr * 36       + ks * 8 + tg + 4]);
                af[mt][3] = __float_as_uint(As[(mr + 8) * 36 + ks * 8 + tg + 4]);
            }
            #pragma unroll
            for (int nt = 0; nt < 4; nt++) {
                int nc = warpN * 32 + nt * 8 + g;
                bf[nt][0] = __float_as_uint(Bs[(ks * 8 + tg) * 132     + nc]);
                bf[nt][1] = __float_as_uint(Bs[(ks * 8 + tg + 4) * 132 + nc]);
            }
            #pragma unroll
            for (int mt = 0; mt < NMT; mt++)
                #pragma unroll
                for (int nt = 0; nt < 4; nt++)
                    asm volatile(
                        "mma.sync.aligned.m16n8k8.row.col.f32.tf32.tf32.f32 "
                        "{%0,%1,%2,%3}, {%4,%5,%6,%7}, {%8,%9}, {%0,%1,%2,%3};"
                        : "+f"(acc[mt][nt][0]), "+f"(acc[mt][nt][1]),
                          "+f"(acc[mt][nt][2]), "+f"(acc[mt][nt][3])
                        : "r"(af[mt][0]), "r"(af[mt][1]), "r"(af[mt][2]), "r"(af[mt][3]),
                          "r"(bf[nt][0]), "r"(bf[nt][1]));
        }
        __syncthreads();
    }

    #pragma unroll
    for (int mt = 0; mt < NMT; mt++) {
        int r0 = m0 + warpM * (MT / 2) + mt * 16 + g;
        #pragma unroll
        for (int nt = 0; nt < 4; nt++) {
            int c0 = n0 + warpN * 32 + nt * 8 + tg * 2;
            if (c0 < Nn) {
                float b0 = (bias && c0 < nBias) ? bias[c0] : 0.f;
                float b1 = (bias && c0 + 1 < nBias) ? bias[c0 + 1] : 0.f;
                float2 v0 = make_float2(acc[mt][nt][0] + b0, acc[mt][nt][1] + b1);
                float2 v1 = make_float2(acc[mt][nt][2] + b0, acc[mt][nt][3] + b1);
                *reinterpret_cast<float2*>(&Cc[(size_t)r0 * Nn + c0]) = v0;
                *reinterpret_cast<float2*>(&Cc[(size_t)(r0 + 8) * Nn + c0]) = v1;
            }
        }
    }
}

// ---------------- dedicated N=3, K=832 GEMM (offset convs of k=1 layers) ------
__global__ void k_gemm_n3(const float* __restrict__ A, const float* __restrict__ Bm,
                          const float* __restrict__ bias, float* __restrict__ out) {
    __shared__ float Bs[832 * 3];
    int tid = threadIdx.x;
    for (int i = tid; i < 832 * 3; i += 256) Bs[i] = Bm[i];
    __syncthreads();
    int warp = tid >> 5, lane = tid & 31;
    int m = blockIdx.x * 8 + warp;
    const float4* aRow = reinterpret_cast<const float4*>(A + (size_t)m * 832);
    float s0 = 0.f, s1 = 0.f, s2 = 0.f;
    #pragma unroll
    for (int j = 0; j < 7; j++) {
        int q = lane + j * 32;
        if (q < 208) {
            float4 v = aRow[q];
            int k = q * 4;
            s0 = fmaf(v.x, Bs[(k+0)*3+0], s0); s1 = fmaf(v.x, Bs[(k+0)*3+1], s1); s2 = fmaf(v.x, Bs[(k+0)*3+2], s2);
            s0 = fmaf(v.y, Bs[(k+1)*3+0], s0); s1 = fmaf(v.y, Bs[(k+1)*3+1], s1); s2 = fmaf(v.y, Bs[(k+1)*3+2], s2);
            s0 = fmaf(v.z, Bs[(k+2)*3+0], s0); s1 = fmaf(v.z, Bs[(k+2)*3+1], s1); s2 = fmaf(v.z, Bs[(k+2)*3+2], s2);
            s0 = fmaf(v.w, Bs[(k+3)*3+0], s0); s1 = fmaf(v.w, Bs[(k+3)*3+1], s1); s2 = fmaf(v.w, Bs[(k+3)*3+2], s2);
        }
    }
    #pragma unroll
    for (int o = 16; o; o >>= 1) {
        s0 += __shfl_xor_sync(0xffffffffu, s0, o);
        s1 += __shfl_xor_sync(0xffffffffu, s1, o);
        s2 += __shfl_xor_sync(0xffffffffu, s2, o);
    }
    if (lane == 0) {
        out[(size_t)m * 3 + 0] = s0 + bias[0];
        out[(size_t)m * 3 + 1] = s1 + bias[1];
        out[(size_t)m * 3 + 2] = s2 + bias[2];
    }
}

// ---------------- k=1 trilinear sampling (one tap) ----------------------------
__global__ void k_sample(const float* __restrict__ src, const float* __restrict__ off,
                         float* __restrict__ samp, int C) {
    int m  = blockIdx.x;
    int b = m / SPA, s = m - b * SPA;
    int t = s / (HH * WW); int rem = s - t * HH * WW;
    int h = rem / WW, w = rem - h * WW;
    const float* op = off + (size_t)m * 3;
    float tc = (float)t + op[0];
    float hc = (float)h + op[1];
    float wc = (float)w + op[2];
    float tf = floorf(tc), hf = floorf(hc), wf = floorf(wc);
    float ft = tc - tf, fh = hc - hf, fw = wc - wf;
    int t0 = (int)tf, h0 = (int)hf, w0 = (int)wf;

    float wgt[8]; const float* ptr[8];
    #pragma unroll
    for (int ci = 0; ci < 8; ci++) {
        int dt = ci >> 2, dh = (ci >> 1) & 1, dw = ci & 1;
        int ti = t0 + dt, hi = h0 + dh, wi = w0 + dw;
        bool valid = (ti >= 0) && (ti < TT) && (hi >= 0) && (hi < HH) && (wi >= 0) && (wi < WW);
        float wv = (dt ? ft : 1.f - ft) * (dh ? fh : 1.f - fh) * (dw ? fw : 1.f - fw);
        wgt[ci] = valid ? wv : 0.f;
        int tic = min(max(ti, 0), TT - 1);
        int hic = min(max(hi, 0), HH - 1);
        int wic = min(max(wi, 0), WW - 1);
        ptr[ci] = src + ((size_t)b * SPA + (tic * HH + hic) * WW + wic) * C;
    }
    float* dst = samp + (size_t)m * C;
    for (int c = threadIdx.x * 4; c < C; c += blockDim.x * 4) {
        float4 acc = make_float4(0.f, 0.f, 0.f, 0.f);
        #pragma unroll
        for (int ci = 0; ci < 8; ci++) {
            float4 v = *reinterpret_cast<const float4*>(ptr[ci] + c);
            acc.x = fmaf(wgt[ci], v.x, acc.x);
            acc.y = fmaf(wgt[ci], v.y, acc.y);
            acc.z = fmaf(wgt[ci], v.z, acc.z);
            acc.w = fmaf(wgt[ci], v.w, acc.w);
        }
        acc.x = f2tff(acc.x); acc.y = f2tff(acc.y);
        acc.z = f2tff(acc.z); acc.w = f2tff(acc.w);
        *reinterpret_cast<float4*>(dst + c) = acc;
    }
}

// ---------------- k=3 trilinear sampling: one CTA per position, 27 taps -------
__global__ void k_sample3(const float* __restrict__ src, const float* __restrict__ off,
                          float* __restrict__ samp, int C) {
    __shared__ float sw[27][8];
    __shared__ int   sb[27][8];
    int m = blockIdx.x;
    int b = m / SPA, s = m - b * SPA;
    int t = s / (HH * WW); int rem = s - t * HH * WW;
    int h = rem / WW, w = rem - h * WW;
    int tid = threadIdx.x;
    if (tid < 27) {
        int kt = tid / 9, kh = (tid / 3) % 3, kw = tid % 3;
        const float* op = off + (size_t)m * 96 + tid * 3;
        float tc = (float)(t - 1 + kt) + op[0];
        float hc = (float)(h - 1 + kh) + op[1];
        float wc = (float)(w - 1 + kw) + op[2];
        float tf = floorf(tc), hf = floorf(hc), wf = floorf(wc);
        float ft = tc - tf, fh = hc - hf, fw = wc - wf;
        int t0 = (int)tf, h0 = (int)hf, w0 = (int)wf;
        #pragma unroll
        for (int ci = 0; ci < 8; ci++) {
            int dt = ci >> 2, dh = (ci >> 1) & 1, dw = ci & 1;
            int ti = t0 + dt, hi = h0 + dh, wi = w0 + dw;
            bool valid = (ti >= 0) && (ti < TT) && (hi >= 0) && (hi < HH) && (wi >= 0) && (wi < WW);
            float wv = (dt ? ft : 1.f - ft) * (dh ? fh : 1.f - fh) * (dw ? fw : 1.f - fw);
            sw[tid][ci] = valid ? wv : 0.f;
            int tic = min(max(ti, 0), TT - 1);
            int hic = min(max(hi, 0), HH - 1);
            int wic = min(max(wi, 0), WW - 1);
            sb[tid][ci] = b * SPA + (tic * HH + hic) * WW + wic;
        }
    }
    __syncthreads();
    int nC4 = C >> 2;
    int items = 27 * nC4;
    float* dst = samp + (size_t)m * 27 * C;
    for (int it = tid; it < items; it += blockDim.x) {
        int kk = it / nC4, c4 = it - kk * nC4;
        float4 acc = make_float4(0.f, 0.f, 0.f, 0.f);
        #pragma unroll
        for (int ci = 0; ci < 8; ci++) {
            float wv = sw[kk][ci];
            const float4* p = reinterpret_cast<const float4*>(src + (size_t)sb[kk][ci] * C) + c4;
            float4 v = *p;
            acc.x = fmaf(wv, v.x, acc.x);
            acc.y = fmaf(wv, v.y, acc.y);
            acc.z = fmaf(wv, v.z, acc.z);
            acc.w = fmaf(wv, v.w, acc.w);
        }
        acc.x = f2tff(acc.x); acc.y = f2tff(acc.y);
        acc.z = f2tff(acc.z); acc.w = f2tff(acc.w);
        reinterpret_cast<float4*>(dst)[(size_t)kk * nC4 + c4] = acc;
    }
}

// ---------------- k=3 im2col: one CTA per position, 27 taps -------------------
__global__ void k_im2col3(const float* __restrict__ src, float* __restrict__ outm, int C) {
    __shared__ int sidx[27];
    __shared__ int svalid[27];
    int m = blockIdx.x;
    int b = m / SPA, s = m - b * SPA;
    int t = s / (HH * WW); int rem = s - t * HH * WW;
    int h = rem / WW, w = rem - h * WW;
    int tid = threadIdx.x;
    if (tid < 27) {
        int kt = tid / 9, kh = (tid / 3) % 3, kw = tid % 3;
        int ti = t + kt - 1, hi = h + kh - 1, wi = w + kw - 1;
        bool valid = (ti >= 0) && (ti < TT) && (hi >= 0) && (hi < HH) && (wi >= 0) && (wi < WW);
        svalid[tid] = valid;
        sidx[tid] = b * SPA + (valid ? (ti * HH + hi) * WW + wi : 0);
    }
    __syncthreads();
    int nC4 = C >> 2;
    int items = 27 * nC4;
    float* dst = outm + (size_t)m * 27 * C;
    for (int it = tid; it < items; it += blockDim.x) {
        int kk = it / nC4, c4 = it - kk * nC4;
        float4 v = make_float4(0.f, 0.f, 0.f, 0.f);
        if (svalid[kk])
            v = reinterpret_cast<const float4*>(src + (size_t)sidx[kk] * C)[c4];
        v.x = f2tff(v.x); v.y = f2tff(v.y);
        v.z = f2tff(v.z); v.w = f2tff(v.w);
        reinterpret_cast<float4*>(dst)[(size_t)kk * nC4 + c4] = v;
    }
}

// ---------------- per-channel batch stats (mean, biased var) ------------------
__global__ void k_stats(const float* __restrict__ Cm, float* __restrict__ stats, int Nn) {
    int n = blockIdx.x * 32 + threadIdx.x;
    float s = 0.f, s2 = 0.f;
    if (n < Nn) {
        for (int m = threadIdx.y; m < MTOT; m += 8) {
            float v = Cm[(size_t)m * Nn + n];
            s += v; s2 += v * v;
        }
    }
    __shared__ float sh[8][32], sh2[8][32];
    sh[threadIdx.y][threadIdx.x] = s;
    sh2[threadIdx.y][threadIdx.x] = s2;
    __syncthreads();
    if (threadIdx.y == 0 && n < Nn) {
        #pragma unroll
        for (int i = 1; i < 8; i++) { s += sh[i][threadIdx.x]; s2 += sh2[i][threadIdx.x]; }
        float mean = s / (float)MTOT;
        float var  = s2 / (float)MTOT - mean * mean;
        stats[n]       = mean;
        stats[512 + n] = var;
    }
}

// ---------------- BN + ReLU, channels-last output (intermediates) -------------
__global__ void k_bnout_cl(const float* __restrict__ Cm, const float* __restrict__ stats,
                           const float* __restrict__ gamma, const float* __restrict__ beta,
                           float* __restrict__ outp, int Nn) {
    size_t idx = (size_t)blockIdx.x * blockDim.x + threadIdx.x;
    size_t tot = (size_t)MTOT * Nn;
    if (idx >= tot) return;
    int n = (int)(idx % Nn);
    float sc = gamma[n] * rsqrtf(stats[512 + n] + 1e-5f);
    float v  = fmaf(Cm[idx] - stats[n], sc, beta[n]);
    outp[idx] = fmaxf(v, 0.f);
}

// ---------------- BN + ReLU + tiled transpose into NCDHW concat output --------
__global__ void k_bnout_t(const float* __restrict__ Cm, const float* __restrict__ stats,
                          const float* __restrict__ gamma, const float* __restrict__ beta,
                          float* __restrict__ outp, int Nn, int ch0) {
    __shared__ float tile[32][33];
    int b = blockIdx.z, s0 = blockIdx.x * 32, n0 = blockIdx.y * 32;
    int tx = threadIdx.x, ty = threadIdx.y;
    int n = n0 + tx;
    float mean = stats[n];
    float sc = gamma[n] * rsqrtf(stats[512 + n] + 1e-5f);
    float bt = beta[n];
    #pragma unroll
    for (int i = ty; i < 32; i += 8) {
        float v = fmaf(Cm[((size_t)b * SPA + s0 + i) * Nn + n] - mean, sc, bt);
        tile[i][tx] = fmaxf(v, 0.f);
    }
    __syncthreads();
    #pragma unroll
    for (int i = ty; i < 32; i += 8)
        outp[((size_t)b * 832 + ch0 + n0 + i) * SPA + s0 + tx] = tile[tx][i];
}

// ============================ host orchestration ==============================
static const int GEMM_SMEM_128 = (3 * 128 * 36 + 3 * 32 * 132) * 4;  // 105,984 B
static const int GEMM_SMEM_64  = (3 * 64 * 36 + 3 * 32 * 132) * 4;   //  78,336 B

static void run_gemm_pipe(const float* A, const float* Bm, const float* bias, int nBias,
                          float* C, int Nn, int Kn) {
    static bool attrSet = false;
    if (!attrSet) {
        cudaFuncSetAttribute(k_gemm_pipe<128>, cudaFuncAttributeMaxDynamicSharedMemorySize, GEMM_SMEM_128);
        cudaFuncSetAttribute(k_gemm_pipe<64>,  cudaFuncAttributeMaxDynamicSharedMemorySize, GEMM_SMEM_64);
        attrSet = true;
    }
    if (Nn <= 128) {
        dim3 grid(1, MTOT / 64);
        k_gemm_pipe<64><<<grid, 256, GEMM_SMEM_64>>>(A, Bm, bias, nBias, C, Nn, Kn);
    } else {
        dim3 grid((Nn + 127) / 128, MTOT / 128);
        k_gemm_pipe<128><<<grid, 256, GEMM_SMEM_128>>>(A, Bm, bias, nBias, C, Nn, Kn);
    }
}

static void run_bn(const float* conv, float* stats, const float* g, const float* bt,
                   float* outp, int Cout, int mode, int ch0) {
    k_stats<<<(Cout + 31) / 32, dim3(32, 8)>>>(conv, stats, Cout);
    if (mode == 0) {
        size_t tot = (size_t)MTOT * Cout;
        k_bnout_cl<<<(unsigned)((tot + 255) / 256), 256>>>(conv, stats, g, bt, outp, Cout);
    } else {
        dim3 grid(SPA / 32, Cout / 32, BB);
        k_bnout_t<<<grid, dim3(32, 8)>>>(conv, stats, g, bt, outp, Cout, ch0);
    }
}

static void run_k1(const float* srcT, int Cin, int Cout,
                   const float* woffT, const float* boffp, const float* wTp,
                   const float* g, const float* bt,
                   float* offb, float* samp, float* conv, float* stats,
                   float* outp, int mode, int ch0) {
    k_gemm_n3<<<MTOT / 8, 256>>>(srcT, woffT, boffp, offb);          // Cin == 832 always
    k_sample<<<MTOT, 128>>>(srcT, offb, samp, Cin);
    run_gemm_pipe(samp, wTp, nullptr, 0, conv, Cout, Cin);
    run_bn(conv, stats, g, bt, outp, Cout, mode, ch0);
}

static void run_k3(const float* srcT, int Cin, int Cout,
                   const float* woffT, const float* boffp, const float* wTp,
                   const float* g, const float* bt,
                   float* offb, float* samp, float* conv, float* stats,
                   float* outp, int mode, int ch0) {
    int Kd = 27 * Cin;
    int blk = (Cin >= 128) ? 256 : 128;
    k_im2col3<<<MTOT, blk>>>(srcT, samp, Cin);
    run_gemm_pipe(samp, woffT, boffp, 81, offb, 96, Kd);   // offsets padded N=96
    k_sample3<<<MTOT, blk>>>(srcT, offb, samp, Cin);
    run_gemm_pipe(samp, wTp, nullptr, 0, conv, Cout, Kd);
    run_bn(conv, stats, g, bt, outp, Cout, mode, ch0);
}

extern "C" void kernel_launch(void* const* d_in, const int* in_sizes, int n_in,
                              void* d_out, int out_size) {
    const float* x = (const float*)d_in[0];
    const float *woff[6], *boff[6], *wcv[6], *gam[6], *bet[6];
    for (int i = 0; i < 6; i++) {
        woff[i] = (const float*)d_in[1 + 5 * i];
        boff[i] = (const float*)d_in[2 + 5 * i];
        wcv[i]  = (const float*)d_in[3 + 5 * i];
        gam[i]  = (const float*)d_in[4 + 5 * i];
        bet[i]  = (const float*)d_in[5 + 5 * i];
    }
    float *xT, *xmT, *x1a, *x2a, *samp, *conv, *offb, *stats, *wT, *woffT;
    cudaGetSymbolAddress((void**)&xT,    g_xT);
    cudaGetSymbolAddress((void**)&xmT,   g_xmT);
    cudaGetSymbolAddress((void**)&x1a,   g_x1a);
    cudaGetSymbolAddress((void**)&x2a,   g_x2a);
    cudaGetSymbolAddress((void**)&samp,  g_samp);
    cudaGetSymbolAddress((void**)&conv,  g_conv);
    cudaGetSymbolAddress((void**)&offb,  g_offb);
    cudaGetSymbolAddress((void**)&stats, g_stats);
    cudaGetSymbolAddress((void**)&wT,    g_wT);
    cudaGetSymbolAddress((void**)&woffT, g_woffT);
    float* out = (float*)d_out;

    const int CIN[6]  = {832, 832, 160, 832, 32, 832};
    const int COUT[6] = {256, 160, 320, 32, 128, 128};
    const int KK[6]   = {1, 1, 27, 1, 27, 1};
    size_t wtoff[6], wooff[6];
    {
        size_t a = 0, bsz = 0;
        for (int i = 0; i < 6; i++) { wtoff[i] = a; a += (size_t)KK[i] * CIN[i] * COUT[i]; }
        for (int i = 0; i < 6; i++) {
            wooff[i] = bsz;
            bsz += (KK[i] == 1) ? (size_t)CIN[i] * 3 : (size_t)KK[i] * CIN[i] * 96;
        }
    }

    // launch #1: fused prep (transpose + all 12 weight transposes)
    {
        WJobs jb;
        int pos = 0;
        for (int i = 0; i < 6; i++) {
            jb.src[i] = wcv[i]; jb.dst[i] = wT + wtoff[i];
            jb.cout[i] = COUT[i]; jb.coutpad[i] = COUT[i];
            jb.cin[i] = CIN[i]; jb.kk[i] = KK[i]; jb.cvt[i] = 1;
            jb.start[i] = pos; pos += KK[i] * CIN[i] * COUT[i];
        }
        for (int i = 0; i < 6; i++) {
            int j = 6 + i;
            jb.src[j] = woff[i]; jb.dst[j] = woffT + wooff[i];
            if (KK[i] == 1) { jb.cout[j] = 3;  jb.coutpad[j] = 3;  jb.cvt[j] = 0; }
            else            { jb.cout[j] = 81; jb.coutpad[j] = 96; jb.cvt[j] = 1; }
            jb.cin[j] = CIN[i]; jb.kk[j] = KK[i];
            jb.start[j] = pos;
            pos += (KK[i] == 1) ? CIN[i] * 3 : KK[i] * CIN[i] * 96;
        }
        jb.start[12] = pos;
        int wBlocks = (pos + 255) / 256;
        k_prep<<<NT_BLOCKS + wBlocks, 256>>>(jb, x, xT);
    }

    // branch 0
    run_k1(xT, 832, 256, woffT + wooff[0], boff[0], wT + wtoff[0], gam[0], bet[0],
           offb, samp, conv, stats, out, 1, 0);

    // branch 1
    run_k1(xT, 832, 160, woffT + wooff[1], boff[1], wT + wtoff[1], gam[1], bet[1],
           offb, samp, conv, stats, x1a, 0, 0);
    run_k3(x1a, 160, 320, woffT + wooff[2], boff[2], wT + wtoff[2], gam[2], bet[2],
           offb, samp, conv, stats, out, 1, 256);

    // branch 2
    run_k1(xT, 832, 32, woffT + wooff[3], boff[3], wT + wtoff[3], gam[3], bet[3],
           offb, samp, conv, stats, x2a, 0, 0);
    run_k3(x2a, 32, 128, woffT + wooff[4], boff[4], wT + wtoff[4], gam[4], bet[4],
           offb, samp, conv, stats, out, 1, 576);

    // branch 3: separable maxpool -> deform k=1
    {
        float* tmp1 = samp;
        float* tmp2 = samp + (size_t)MTOT * 832;
        int nthr = (int)(((size_t)MTOT * 208 + 255) / 256);
        k_max3<<<nthr, 256>>>(xT,   tmp1, 1,       WW);
        k_max3<<<nthr, 256>>>(tmp1, tmp2, WW,      HH);
        k_max3<<<nthr, 256>>>(tmp2, xmT,  HH * WW, TT);
    }
    run_k1(xmT, 832, 128, woffT + wooff[5], boff[5], wT + wtoff[5], gam[5], bet[5],
           offb, samp, conv, stats, out, 1, 704);
}

// round 13
// speedup vs baseline: 1.4043x; 1.4043x over previous
#include <cuda_runtime.h>
#include <cuda_fp16.h>
#include <math.h>
#include <stdint.h>

// Problem constants
#define BB   8
#define TT   8
#define HH   14
#define WW   14
#define SPA  1568          // T*H*W
#define MTOT 12544         // B*SPA
#define KC   32            // GEMM k-chunk (halfs)

// ---------------- scratch (device globals; no allocation allowed) -------------
__device__ float g_xT [(size_t)MTOT * 832];   // x channels-last (fp32)
__device__ float g_xmT[(size_t)MTOT * 832];   // maxpool(x) channels-last (fp32)
__device__ float g_x1a[(size_t)MTOT * 160];   // branch1 intermediate (fp32)
__device__ float g_x2a[(size_t)MTOT * 32];    // branch2 intermediate (fp32)
__device__ float g_samp[(size_t)MTOT * 2160]; // im2col/sampled rows (HALF, 4320 halfs/row max)
__device__ float g_conv[(size_t)MTOT * 384];  // raw conv output (stride = Npad)
__device__ float g_offb[(size_t)MTOT * 128];  // offset field (stride 128 for k=3)
__device__ float g_stats[1024];               // [0..511]=mean, [512..1023]=var
__device__ float g_wT  [2500000];             // packed fp16 weights [K/2][Npad] u32
__device__ float g_woffT[680000];             // offset weights (k1 fp32 / k3 packed fp16)

__device__ __forceinline__ uint32_t h2bits(float a, float b) {
    __half2 h = __floats2half2_rn(a, b);   // a -> low half (even k), b -> high
    return *reinterpret_cast<uint32_t*>(&h);
}

__device__ __forceinline__ void cpa16(uint32_t dst, const void* src) {
    asm volatile("cp.async.cg.shared.global [%0], [%1], 16;" :: "r"(dst), "l"(src));
}

// ---------------- fused prep: transpose x + all weight jobs -------------------
// mode 0: k=1 offset conv -> dst[c*3+o] = src[o*Cin+c]  (fp32)
// mode 1: packed fp16 B   -> dstU32[kp*Npad + n] = half2(w(n,2kp), w(n,2kp+1))
//         where K index = kk*Cin + c, w(n,K) = src[(n*Cin + c)*KT + kk], n>=cout -> 0
struct WJobs {
    const float* src[12];
    float*       dst[12];
    int cout[12], npad[12], cin[12], kt[12], mode[12];
    int start[13];
};
#define NT_BLOCKS (49 * 26 * 8)

__global__ void k_prep(WJobs jb, const float* __restrict__ x, float* __restrict__ xT) {
    int bid = blockIdx.x;
    if (bid < NT_BLOCKS) {
        __shared__ float tile[32][33];
        int sx = bid % 49;
        int cy = (bid / 49) % 26;
        int b  = bid / (49 * 26);
        int s0 = sx * 32, c0 = cy * 32;
        int tx = threadIdx.x % 32, ty = threadIdx.x / 32;
        #pragma unroll
        for (int i = ty; i < 32; i += 8)
            tile[i][tx] = x[((size_t)b * 832 + (c0 + i)) * SPA + s0 + tx];
        __syncthreads();
        #pragma unroll
        for (int i = ty; i < 32; i += 8)
            xT[((size_t)b * SPA + (s0 + i)) * 832 + c0 + tx] = tile[tx][i];
    } else {
        int idx = (bid - NT_BLOCKS) * 256 + threadIdx.x;
        if (idx >= jb.start[12]) return;
        int j = 0;
        #pragma unroll
        for (int i = 1; i < 12; i++) if (idx >= jb.start[i]) j = i;
        int local = idx - jb.start[j];
        int ci = jb.cin[j], KT = jb.kt[j];
        if (jb.mode[j] == 0) {
            int c = local / 3, o = local % 3;
            jb.dst[j][local] = jb.src[j][o * ci + c];
        } else {
            int np = jb.npad[j];
            int kp = local / np, n = local % np;
            float v0 = 0.f, v1 = 0.f;
            if (n < jb.cout[j]) {
                int K0 = 2 * kp, K1 = 2 * kp + 1;
                int kk0 = K0 / ci, c0 = K0 - kk0 * ci;
                int kk1 = K1 / ci, c1 = K1 - kk1 * ci;
                v0 = jb.src[j][((size_t)n * ci + c0) * KT + kk0];
                v1 = jb.src[j][((size_t)n * ci + c1) * KT + kk1];
            }
            jb.dst[j][local] = __uint_as_float(h2bits(v0, v1));
        }
    }
}

// ---------------- separable 3-max along one dim, channels-last ----------------
__global__ void k_max3(const float* __restrict__ in, float* __restrict__ out,
                       int ddiv, int dmod) {
    size_t idx = (size_t)blockIdx.x * blockDim.x + threadIdx.x;
    if (idx >= (size_t)MTOT * 208) return;
    int c4 = (int)(idx % 208);
    size_t m = idx / 208;
    int s = (int)(m % SPA);
    int coord = (s / ddiv) % dmod;
    const float4* p = reinterpret_cast<const float4*>(in) + m * 208 + c4;
    float4 v = *p;
    if (coord > 0) {
        float4 u = *(p - (size_t)ddiv * 208);
        v.x = fmaxf(v.x, u.x); v.y = fmaxf(v.y, u.y);
        v.z = fmaxf(v.z, u.z); v.w = fmaxf(v.w, u.w);
    }
    if (coord < dmod - 1) {
        float4 u = *(p + (size_t)ddiv * 208);
        v.x = fmaxf(v.x, u.x); v.y = fmaxf(v.y, u.y);
        v.z = fmaxf(v.z, u.z); v.w = fmaxf(v.w, u.w);
    }
    reinterpret_cast<float4*>(out)[m * 208 + c4] = v;
}

// ---------------- fp16 tensor GEMM: C[M,Npad] = A[M,K] @ B[K,Npad] ------------
// A: [M][Kn] half (k-contiguous). B: packed [Kn/2][Npad] u32 (half2 pairs, low = even k).
// mma.sync.m16n8k16.row.col f16 -> f32. CTA tile 128x128, warp 64x32.
// 2-stage cp.async, K-chunk = 32 halfs (2 ksteps). Npad mult of 128.
// smem (u32): A stage [128][20] (16 data + 4 pad), B stage [16][136] (128 + 8 pad).
#define ASTG (128 * 20)
#define BSTG (16 * 136)
#define GEMM_SMEM_B ((2 * ASTG + 2 * BSTG) * 4)

__global__ __launch_bounds__(256, 2) void k_gemm_fp16(
    const __half* __restrict__ A, const uint32_t* __restrict__ Bm,
    const float* __restrict__ bias, int nBias,
    float* __restrict__ Cc, int Npad, int Kn)
{
    extern __shared__ uint32_t smu[];
    int tid = threadIdx.x;
    int lane = tid & 31, warp = tid >> 5;
    int warpM = warp & 1, warpN = warp >> 1;
    int m0 = blockIdx.y * 128, n0 = blockIdx.x * 128;
    int g = lane >> 2, tg = lane & 3;

    float acc[4][4][4];
    #pragma unroll
    for (int i = 0; i < 4; i++)
        #pragma unroll
        for (int j = 0; j < 4; j++)
            #pragma unroll
            for (int q = 0; q < 4; q++) acc[i][j][q] = 0.f;

    // A: 2 threads/row, each 16 halfs (2x cp.async 16B)
    const int aRow = tid >> 1;
    const int aColH = (tid & 1) * 16;                 // half offset within chunk
    const __half* aPtr = A + (size_t)(m0 + aRow) * Kn + aColH;
    uint32_t aBase = (uint32_t)__cvta_generic_to_shared(&smu[aRow * 20 + (tid & 1) * 8]);
    // B: 16 threads/row, each 8 u32 (2x cp.async 16B)
    const int bRow = tid >> 4;
    const int bCol = (tid & 15) * 8;
    uint32_t bBase = (uint32_t)__cvta_generic_to_shared(&smu[2 * ASTG + bRow * 136 + bCol]);

    int nChunks = Kn / KC;

    auto issue = [&](int c) {
        int st = c & 1;
        const __half* ap = aPtr + c * KC;
        cpa16(aBase + (uint32_t)st * ASTG * 4,      ap);
        cpa16(aBase + (uint32_t)st * ASTG * 4 + 16, ap + 8);
        const uint32_t* bp = Bm + (size_t)(c * (KC / 2) + bRow) * Npad + n0 + bCol;
        cpa16(bBase + (uint32_t)st * BSTG * 4,      bp);
        cpa16(bBase + (uint32_t)st * BSTG * 4 + 16, bp + 4);
        asm volatile("cp.async.commit_group;");
    };

    issue(0);
    for (int c = 0; c < nChunks; c++) {
        int st = c & 1;
        if (c + 1 < nChunks) {
            issue(c + 1);
            asm volatile("cp.async.wait_group 1;");
        } else {
            asm volatile("cp.async.wait_group 0;");
        }
        __syncthreads();

        const uint32_t* As = smu + (size_t)st * ASTG;
        const uint32_t* Bs = smu + 2 * ASTG + (size_t)st * BSTG;
        #pragma unroll
        for (int ks = 0; ks < 2; ks++) {
            uint32_t af[4][4], bf[4][2];
            #pragma unroll
            for (int mt = 0; mt < 4; mt++) {
                int mr = warpM * 64 + mt * 16 + g;
                af[mt][0] = As[mr * 20       + ks * 8 + tg];
                af[mt][1] = As[(mr + 8) * 20 + ks * 8 + tg];
                af[mt][2] = As[mr * 20       + ks * 8 + 4 + tg];
                af[mt][3] = As[(mr + 8) * 20 + ks * 8 + 4 + tg];
            }
            #pragma unroll
            for (int nt = 0; nt < 4; nt++) {
                int nc = warpN * 32 + nt * 8 + g;
                bf[nt][0] = Bs[(ks * 8 + tg) * 136     + nc];
                bf[nt][1] = Bs[(ks * 8 + 4 + tg) * 136 + nc];
            }
            #pragma unroll
            for (int mt = 0; mt < 4; mt++)
                #pragma unroll
                for (int nt = 0; nt < 4; nt++)
                    asm volatile(
                        "mma.sync.aligned.m16n8k16.row.col.f32.f16.f16.f32 "
                        "{%0,%1,%2,%3}, {%4,%5,%6,%7}, {%8,%9}, {%0,%1,%2,%3};"
                        : "+f"(acc[mt][nt][0]), "+f"(acc[mt][nt][1]),
                          "+f"(acc[mt][nt][2]), "+f"(acc[mt][nt][3])
                        : "r"(af[mt][0]), "r"(af[mt][1]), "r"(af[mt][2]), "r"(af[mt][3]),
                          "r"(bf[nt][0]), "r"(bf[nt][1]));
        }
        __syncthreads();
    }

    #pragma unroll
    for (int mt = 0; mt < 4; mt++) {
        int r0 = m0 + warpM * 64 + mt * 16 + g;
        #pragma unroll
        for (int nt = 0; nt < 4; nt++) {
            int c0 = n0 + warpN * 32 + nt * 8 + tg * 2;
            float b0 = (bias && c0 < nBias) ? bias[c0] : 0.f;
            float b1 = (bias && c0 + 1 < nBias) ? bias[c0 + 1] : 0.f;
            float2 v0 = make_float2(acc[mt][nt][0] + b0, acc[mt][nt][1] + b1);
            float2 v1 = make_float2(acc[mt][nt][2] + b0, acc[mt][nt][3] + b1);
            *reinterpret_cast<float2*>(&Cc[(size_t)r0 * Npad + c0]) = v0;
            *reinterpret_cast<float2*>(&Cc[(size_t)(r0 + 8) * Npad + c0]) = v1;
        }
    }
}

// ---------------- dedicated N=3, K=832 GEMM (offset convs of k=1 layers) ------
__global__ void k_gemm_n3(const float* __restrict__ A, const float* __restrict__ Bm,
                          const float* __restrict__ bias, float* __restrict__ out) {
    __shared__ float Bs[832 * 3];
    int tid = threadIdx.x;
    for (int i = tid; i < 832 * 3; i += 256) Bs[i] = Bm[i];
    __syncthreads();
    int warp = tid >> 5, lane = tid & 31;
    int m = blockIdx.x * 8 + warp;
    const float4* aRow = reinterpret_cast<const float4*>(A + (size_t)m * 832);
    float s0 = 0.f, s1 = 0.f, s2 = 0.f;
    #pragma unroll
    for (int j = 0; j < 7; j++) {
        int q = lane + j * 32;
        if (q < 208) {
            float4 v = aRow[q];
            int k = q * 4;
            s0 = fmaf(v.x, Bs[(k+0)*3+0], s0); s1 = fmaf(v.x, Bs[(k+0)*3+1], s1); s2 = fmaf(v.x, Bs[(k+0)*3+2], s2);
            s0 = fmaf(v.y, Bs[(k+1)*3+0], s0); s1 = fmaf(v.y, Bs[(k+1)*3+1], s1); s2 = fmaf(v.y, Bs[(k+1)*3+2], s2);
            s0 = fmaf(v.z, Bs[(k+2)*3+0], s0); s1 = fmaf(v.z, Bs[(k+2)*3+1], s1); s2 = fmaf(v.z, Bs[(k+2)*3+2], s2);
            s0 = fmaf(v.w, Bs[(k+3)*3+0], s0); s1 = fmaf(v.w, Bs[(k+3)*3+1], s1); s2 = fmaf(v.w, Bs[(k+3)*3+2], s2);
        }
    }
    #pragma unroll
    for (int o = 16; o; o >>= 1) {
        s0 += __shfl_xor_sync(0xffffffffu, s0, o);
        s1 += __shfl_xor_sync(0xffffffffu, s1, o);
        s2 += __shfl_xor_sync(0xffffffffu, s2, o);
    }
    if (lane == 0) {
        out[(size_t)m * 3 + 0] = s0 + bias[0];
        out[(size_t)m * 3 + 1] = s1 + bias[1];
        out[(size_t)m * 3 + 2] = s2 + bias[2];
    }
}

// ---------------- k=1 trilinear sampling (one tap) -> half --------------------
__global__ void k_sample(const float* __restrict__ src, const float* __restrict__ off,
                         __half* __restrict__ samp, int C) {
    int m  = blockIdx.x;
    int b = m / SPA, s = m - b * SPA;
    int t = s / (HH * WW); int rem = s - t * HH * WW;
    int h = rem / WW, w = rem - h * WW;
    const float* op = off + (size_t)m * 3;
    float tc = (float)t + op[0];
    float hc = (float)h + op[1];
    float wc = (float)w + op[2];
    float tf = floorf(tc), hf = floorf(hc), wf = floorf(wc);
    float ft = tc - tf, fh = hc - hf, fw = wc - wf;
    int t0 = (int)tf, h0 = (int)hf, w0 = (int)wf;

    float wgt[8]; const float* ptr[8];
    #pragma unroll
    for (int ci = 0; ci < 8; ci++) {
        int dt = ci >> 2, dh = (ci >> 1) & 1, dw = ci & 1;
        int ti = t0 + dt, hi = h0 + dh, wi = w0 + dw;
        bool valid = (ti >= 0) && (ti < TT) && (hi >= 0) && (hi < HH) && (wi >= 0) && (wi < WW);
        float wv = (dt ? ft : 1.f - ft) * (dh ? fh : 1.f - fh) * (dw ? fw : 1.f - fw);
        wgt[ci] = valid ? wv : 0.f;
        int tic = min(max(ti, 0), TT - 1);
        int hic = min(max(hi, 0), HH - 1);
        int wic = min(max(wi, 0), WW - 1);
        ptr[ci] = src + ((size_t)b * SPA + (tic * HH + hic) * WW + wic) * C;
    }
    uint2* dst = reinterpret_cast<uint2*>(samp + (size_t)m * C);
    for (int c = threadIdx.x * 4; c < C; c += blockDim.x * 4) {
        float4 acc = make_float4(0.f, 0.f, 0.f, 0.f);
        #pragma unroll
        for (int ci = 0; ci < 8; ci++) {
            float4 v = *reinterpret_cast<const float4*>(ptr[ci] + c);
            acc.x = fmaf(wgt[ci], v.x, acc.x);
            acc.y = fmaf(wgt[ci], v.y, acc.y);
            acc.z = fmaf(wgt[ci], v.z, acc.z);
            acc.w = fmaf(wgt[ci], v.w, acc.w);
        }
        dst[c >> 2] = make_uint2(h2bits(acc.x, acc.y), h2bits(acc.z, acc.w));
    }
}

// ---------------- k=3 trilinear sampling: one CTA per position -> half --------
__global__ void k_sample3(const float* __restrict__ src, const float* __restrict__ off,
                          __half* __restrict__ samp, int C) {
    __shared__ float sw[27][8];
    __shared__ int   sb[27][8];
    int m = blockIdx.x;
    int b = m / SPA, s = m - b * SPA;
    int t = s / (HH * WW); int rem = s - t * HH * WW;
    int h = rem / WW, w = rem - h * WW;
    int tid = threadIdx.x;
    if (tid < 27) {
        int kt = tid / 9, kh = (tid / 3) % 3, kw = tid % 3;
        const float* op = off + (size_t)m * 128 + tid * 3;
        float tc = (float)(t - 1 + kt) + op[0];
        float hc = (float)(h - 1 + kh) + op[1];
        float wc = (float)(w - 1 + kw) + op[2];
        float tf = floorf(tc), hf = floorf(hc), wf = floorf(wc);
        float ft = tc - tf, fh = hc - hf, fw = wc - wf;
        int t0 = (int)tf, h0 = (int)hf, w0 = (int)wf;
        #pragma unroll
        for (int ci = 0; ci < 8; ci++) {
            int dt = ci >> 2, dh = (ci >> 1) & 1, dw = ci & 1;
            int ti = t0 + dt, hi = h0 + dh, wi = w0 + dw;
            bool valid = (ti >= 0) && (ti < TT) && (hi >= 0) && (hi < HH) && (wi >= 0) && (wi < WW);
            float wv = (dt ? ft : 1.f - ft) * (dh ? fh : 1.f - fh) * (dw ? fw : 1.f - fw);
            sw[tid][ci] = valid ? wv : 0.f;
            int tic = min(max(ti, 0), TT - 1);
            int hic = min(max(hi, 0), HH - 1);
            int wic = min(max(wi, 0), WW - 1);
            sb[tid][ci] = b * SPA + (tic * HH + hic) * WW + wic;
        }
    }
    __syncthreads();
    int nC4 = C >> 2;
    int items = 27 * nC4;
    uint2* dst = reinterpret_cast<uint2*>(samp + (size_t)m * 27 * C);
    for (int it = tid; it < items; it += blockDim.x) {
        int kk = it / nC4, c4 = it - kk * nC4;
        float4 acc = make_float4(0.f, 0.f, 0.f, 0.f);
        #pragma unroll
        for (int ci = 0; ci < 8; ci++) {
            float wv = sw[kk][ci];
            float4 v = reinterpret_cast<const float4*>(src + (size_t)sb[kk][ci] * C)[c4];
            acc.x = fmaf(wv, v.x, acc.x);
            acc.y = fmaf(wv, v.y, acc.y);
            acc.z = fmaf(wv, v.z, acc.z);
            acc.w = fmaf(wv, v.w, acc.w);
        }
        dst[(size_t)kk * nC4 + c4] = make_uint2(h2bits(acc.x, acc.y), h2bits(acc.z, acc.w));
    }
}

// ---------------- k=3 im2col: one CTA per position -> half --------------------
__global__ void k_im2col3(const float* __restrict__ src, __half* __restrict__ outm, int C) {
    __shared__ int sidx[27];
    __shared__ int svalid[27];
    int m = blockIdx.x;
    int b = m / SPA, s = m - b * SPA;
    int t = s / (HH * WW); int rem = s - t * HH * WW;
    int h = rem / WW, w = rem - h * WW;
    int tid = threadIdx.x;
    if (tid < 27) {
        int kt = tid / 9, kh = (tid / 3) % 3, kw = tid % 3;
        int ti = t + kt - 1, hi = h + kh - 1, wi = w + kw - 1;
        bool valid = (ti >= 0) && (ti < TT) && (hi >= 0) && (hi < HH) && (wi >= 0) && (wi < WW);
        svalid[tid] = valid;
        sidx[tid] = b * SPA + (valid ? (ti * HH + hi) * WW + wi : 0);
    }
    __syncthreads();
    int nC4 = C >> 2;
    int items = 27 * nC4;
    uint2* dst = reinterpret_cast<uint2*>(outm + (size_t)m * 27 * C);
    for (int it = tid; it < items; it += blockDim.x) {
        int kk = it / nC4, c4 = it - kk * nC4;
        float4 v = make_float4(0.f, 0.f, 0.f, 0.f);
        if (svalid[kk])
            v = reinterpret_cast<const float4*>(src + (size_t)sidx[kk] * C)[c4];
        dst[(size_t)kk * nC4 + c4] = make_uint2(h2bits(v.x, v.y), h2bits(v.z, v.w));
    }
}

// ---------------- per-channel batch stats (mean, biased var) ------------------
__global__ void k_stats(const float* __restrict__ Cm, float* __restrict__ stats,
                        int Nn, int stride) {
    int n = blockIdx.x * 32 + threadIdx.x;
    float s = 0.f, s2 = 0.f;
    if (n < Nn) {
        for (int m = threadIdx.y; m < MTOT; m += 8) {
            float v = Cm[(size_t)m * stride + n];
            s += v; s2 += v * v;
        }
    }
    __shared__ float sh[8][32], sh2[8][32];
    sh[threadIdx.y][threadIdx.x] = s;
    sh2[threadIdx.y][threadIdx.x] = s2;
    __syncthreads();
    if (threadIdx.y == 0 && n < Nn) {
        #pragma unroll
        for (int i = 1; i < 8; i++) { s += sh[i][threadIdx.x]; s2 += sh2[i][threadIdx.x]; }
        float mean = s / (float)MTOT;
        float var  = s2 / (float)MTOT - mean * mean;
        stats[n]       = mean;
        stats[512 + n] = var;
    }
}

// ---------------- BN + ReLU, channels-last dense output (intermediates) -------
__global__ void k_bnout_cl(const float* __restrict__ Cm, const float* __restrict__ stats,
                           const float* __restrict__ gamma, const float* __restrict__ beta,
                           float* __restrict__ outp, int Nn, int stride) {
    size_t idx = (size_t)blockIdx.x * blockDim.x + threadIdx.x;
    size_t tot = (size_t)MTOT * Nn;
    if (idx >= tot) return;
    int n = (int)(idx % Nn);
    size_t m = idx / Nn;
    float sc = gamma[n] * rsqrtf(stats[512 + n] + 1e-5f);
    float v  = fmaf(Cm[m * stride + n] - stats[n], sc, beta[n]);
    outp[idx] = fmaxf(v, 0.f);
}

// ---------------- BN + ReLU + tiled transpose into NCDHW concat output --------
__global__ void k_bnout_t(const float* __restrict__ Cm, const float* __restrict__ stats,
                          const float* __restrict__ gamma, const float* __restrict__ beta,
                          float* __restrict__ outp, int stride, int ch0) {
    __shared__ float tile[32][33];
    int b = blockIdx.z, s0 = blockIdx.x * 32, n0 = blockIdx.y * 32;
    int tx = threadIdx.x, ty = threadIdx.y;
    int n = n0 + tx;
    float mean = stats[n];
    float sc = gamma[n] * rsqrtf(stats[512 + n] + 1e-5f);
    float bt = beta[n];
    #pragma unroll
    for (int i = ty; i < 32; i += 8) {
        float v = fmaf(Cm[((size_t)b * SPA + s0 + i) * stride + n] - mean, sc, bt);
        tile[i][tx] = fmaxf(v, 0.f);
    }
    __syncthreads();
    #pragma unroll
    for (int i = ty; i < 32; i += 8)
        outp[((size_t)b * 832 + ch0 + n0 + i) * SPA + s0 + tx] = tile[tx][i];
}

// ============================ host orchestration ==============================
static void run_gemm16(const __half* A, const float* Bm, const float* bias, int nBias,
                       float* C, int Npad, int Kn) {
    static bool attrSet = false;
    if (!attrSet) {
        cudaFuncSetAttribute(k_gemm_fp16, cudaFuncAttributeMaxDynamicSharedMemorySize,
                             GEMM_SMEM_B);
        attrSet = true;
    }
    dim3 grid(Npad / 128, MTOT / 128);
    k_gemm_fp16<<<grid, 256, GEMM_SMEM_B>>>(A, reinterpret_cast<const uint32_t*>(Bm),
                                            bias, nBias, C, Npad, Kn);
}

static void run_bn(const float* conv, float* stats, const float* g, const float* bt,
                   float* outp, int Cout, int stride, int mode, int ch0) {
    k_stats<<<(Cout + 31) / 32, dim3(32, 8)>>>(conv, stats, Cout, stride);
    if (mode == 0) {
        size_t tot = (size_t)MTOT * Cout;
        k_bnout_cl<<<(unsigned)((tot + 255) / 256), 256>>>(conv, stats, g, bt, outp, Cout, stride);
    } else {
        dim3 grid(SPA / 32, Cout / 32, BB);
        k_bnout_t<<<grid, dim3(32, 8)>>>(conv, stats, g, bt, outp, stride, ch0);
    }
}

static void run_k1(const float* srcT, int Cin, int Cout, int Npad,
                   const float* woffT, const float* boffp, const float* wTp,
                   const float* g, const float* bt,
                   float* offb, __half* samp, float* conv, float* stats,
                   float* outp, int mode, int ch0) {
    k_gemm_n3<<<MTOT / 8, 256>>>(srcT, woffT, boffp, offb);   // Cin == 832 always
    k_sample<<<MTOT, 128>>>(srcT, offb, samp, Cin);
    run_gemm16(samp, wTp, nullptr, 0, conv, Npad, Cin);
    run_bn(conv, stats, g, bt, outp, Cout, Npad, mode, ch0);
}

static void run_k3(const float* srcT, int Cin, int Cout, int Npad,
                   const float* woffT, const float* boffp, const float* wTp,
                   const float* g, const float* bt,
                   float* offb, __half* samp, float* conv, float* stats,
                   float* outp, int mode, int ch0) {
    int Kd = 27 * Cin;
    int blk = (Cin >= 128) ? 256 : 128;
    k_im2col3<<<MTOT, blk>>>(srcT, samp, Cin);
    run_gemm16(samp, woffT, boffp, 81, offb, 128, Kd);   // offsets Npad=128
    k_sample3<<<MTOT, blk>>>(srcT, offb, samp, Cin);
    run_gemm16(samp, wTp, nullptr, 0, conv, Npad, Kd);
    run_bn(conv, stats, g, bt, outp, Cout, Npad, mode, ch0);
}

extern "C" void kernel_launch(void* const* d_in, const int* in_sizes, int n_in,
                              void* d_out, int out_size) {
    const float* x = (const float*)d_in[0];
    const float *woff[6], *boff[6], *wcv[6], *gam[6], *bet[6];
    for (int i = 0; i < 6; i++) {
        woff[i] = (const float*)d_in[1 + 5 * i];
        boff[i] = (const float*)d_in[2 + 5 * i];
        wcv[i]  = (const float*)d_in[3 + 5 * i];
        gam[i]  = (const float*)d_in[4 + 5 * i];
        bet[i]  = (const float*)d_in[5 + 5 * i];
    }
    float *xT, *xmT, *x1a, *x2a, *sampf, *conv, *offb, *stats, *wT, *woffT;
    cudaGetSymbolAddress((void**)&xT,    g_xT);
    cudaGetSymbolAddress((void**)&xmT,   g_xmT);
    cudaGetSymbolAddress((void**)&x1a,   g_x1a);
    cudaGetSymbolAddress((void**)&x2a,   g_x2a);
    cudaGetSymbolAddress((void**)&sampf, g_samp);
    cudaGetSymbolAddress((void**)&conv,  g_conv);
    cudaGetSymbolAddress((void**)&offb,  g_offb);
    cudaGetSymbolAddress((void**)&stats, g_stats);
    cudaGetSymbolAddress((void**)&wT,    g_wT);
    cudaGetSymbolAddress((void**)&woffT, g_woffT);
    __half* samp = reinterpret_cast<__half*>(sampf);
    float* out = (float*)d_out;

    const int CIN[6]  = {832, 832, 160, 832, 32, 832};
    const int COUT[6] = {256, 160, 320, 32, 128, 128};
    const int NPAD[6] = {256, 256, 384, 128, 128, 128};
    const int KK[6]   = {1, 1, 27, 1, 27, 1};
    size_t wtoff[6], wooff[6];
    {
        size_t a = 0, bsz = 0;
        for (int i = 0; i < 6; i++) {
            wtoff[i] = a;
            a += (size_t)(KK[i] * CIN[i] / 2) * NPAD[i];          // packed u32 count
        }
        for (int i = 0; i < 6; i++) {
            wooff[i] = bsz;
            bsz += (KK[i] == 1) ? (size_t)CIN[i] * 3              // fp32
                                : (size_t)(KK[i] * CIN[i] / 2) * 128;  // packed u32
        }
    }

    // launch #1: fused prep (transpose + all 12 weight jobs)
    {
        WJobs jb;
        int pos = 0;
        for (int i = 0; i < 6; i++) {        // main conv -> packed fp16 [K/2][Npad]
            jb.src[i] = wcv[i]; jb.dst[i] = wT + wtoff[i];
            jb.cout[i] = COUT[i]; jb.npad[i] = NPAD[i];
            jb.cin[i] = CIN[i]; jb.kt[i] = KK[i]; jb.mode[i] = 1;
            jb.start[i] = pos; pos += (KK[i] * CIN[i] / 2) * NPAD[i];
        }
        for (int i = 0; i < 6; i++) {        // offset conv
            int j = 6 + i;
            jb.src[j] = woff[i]; jb.dst[j] = woffT + wooff[i];
            if (KK[i] == 1) {
                jb.cout[j] = 3; jb.npad[j] = 3; jb.mode[j] = 0;
                jb.cin[j] = CIN[i]; jb.kt[j] = 1;
                jb.start[j] = pos; pos += CIN[i] * 3;
            } else {
                jb.cout[j] = 81; jb.npad[j] = 128; jb.mode[j] = 1;
                jb.cin[j] = CIN[i]; jb.kt[j] = 27;
                jb.start[j] = pos; pos += (27 * CIN[i] / 2) * 128;
            }
        }
        jb.start[12] = pos;
        int wBlocks = (pos + 255) / 256;
        k_prep<<<NT_BLOCKS + wBlocks, 256>>>(jb, x, xT);
    }

    // branch 0 (launch #4 is the L0 fp16 GEMM -> profiled)
    run_k1(xT, 832, 256, 256, woffT + wooff[0], boff[0], wT + wtoff[0], gam[0], bet[0],
           offb, samp, conv, stats, out, 1, 0);

    // branch 1
    run_k1(xT, 832, 160, 256, woffT + wooff[1], boff[1], wT + wtoff[1], gam[1], bet[1],
           offb, samp, conv, stats, x1a, 0, 0);
    run_k3(x1a, 160, 320, 384, woffT + wooff[2], boff[2], wT + wtoff[2], gam[2], bet[2],
           offb, samp, conv, stats, out, 1, 256);

    // branch 2
    run_k1(xT, 832, 32, 128, woffT + wooff[3], boff[3], wT + wtoff[3], gam[3], bet[3],
           offb, samp, conv, stats, x2a, 0, 0);
    run_k3(x2a, 32, 128, 128, woffT + wooff[4], boff[4], wT + wtoff[4], gam[4], bet[4],
           offb, samp, conv, stats, out, 1, 576);

    // branch 3: separable maxpool -> deform k=1
    {
        float* tmp1 = sampf;
        float* tmp2 = sampf + (size_t)MTOT * 832;
        // NOTE: g_samp holds MTOT*2160 floats >= 2*MTOT*832 ✓
        int nthr = (int)(((size_t)MTOT * 208 + 255) / 256);
        k_max3<<<nthr, 256>>>(xT,   tmp1, 1,       WW);
        k_max3<<<nthr, 256>>>(tmp1, tmp2, WW,      HH);
        k_max3<<<nthr, 256>>>(tmp2, xmT,  HH * WW, TT);
    }
    run_k1(xmT, 832, 128, 128, woffT + wooff[5], boff[5], wT + wtoff[5], gam[5], bet[5],
           offb, samp, conv, stats, out, 1, 704);
}

// round 15
// speedup vs baseline: 1.4700x; 1.0468x over previous
#include <cuda_runtime.h>
#include <cuda_fp16.h>
#include <math.h>
#include <stdint.h>

// Problem constants
#define BB   8
#define TT   8
#define HH   14
#define WW   14
#define SPA  1568          // T*H*W
#define MTOT 12544         // B*SPA
#define KC   32            // GEMM k-chunk (halfs)

// ---------------- scratch (device globals; no allocation allowed) -------------
__device__ __half g_xT [(size_t)MTOT * 832];  // x channels-last (fp16)
__device__ __half g_xmT[(size_t)MTOT * 832];  // maxpool(x) channels-last (fp16)
__device__ __half g_x1a[(size_t)MTOT * 160];  // branch1 intermediate (fp16)
__device__ __half g_x2a[(size_t)MTOT * 32];   // branch2 intermediate (fp16)
__device__ float g_samp[(size_t)MTOT * 2160]; // im2col/sampled rows (HALF, 4320/row max)
__device__ float g_conv[(size_t)MTOT * 384];  // raw conv output (stride = Npad)
__device__ float g_offb[(size_t)MTOT * 128];  // offset field (stride 128 for k=3)
__device__ float g_stats[1024];               // [0..511]=mean, [512..1023]=var
__device__ float g_wT  [2500000];             // packed fp16 weights [K/2][Npad] u32
__device__ float g_woffT[680000];             // offset weights (k1 fp32 / k3 packed fp16)

__device__ __forceinline__ uint32_t h2bits(float a, float b) {
    __half2 h = __floats2half2_rn(a, b);
    return *reinterpret_cast<uint32_t*>(&h);
}
__device__ __forceinline__ float2 h2f(uint32_t u) {
    return __half22float2(*reinterpret_cast<__half2*>(&u));
}
__device__ __forceinline__ uint32_t umax2(uint32_t a, uint32_t b) {
    __half2 r = __hmax2(*reinterpret_cast<__half2*>(&a), *reinterpret_cast<__half2*>(&b));
    return *reinterpret_cast<uint32_t*>(&r);
}

__device__ __forceinline__ void cpa16(uint32_t dst, const void* src) {
    asm volatile("cp.async.cg.shared.global [%0], [%1], 16;" :: "r"(dst), "l"(src));
}

// ---------------- fused prep: transpose x -> fp16 + all weight jobs -----------
struct WJobs {
    const float* src[12];
    float*       dst[12];
    int cout[12], npad[12], cin[12], kt[12], mode[12];
    int start[13];
};
#define NT_BLOCKS (49 * 26 * 8)

__global__ void k_prep(WJobs jb, const float* __restrict__ x, __half* __restrict__ xT) {
    int bid = blockIdx.x;
    if (bid < NT_BLOCKS) {
        __shared__ float tile[32][33];
        int sx = bid % 49;
        int cy = (bid / 49) % 26;
        int b  = bid / (49 * 26);
        int s0 = sx * 32, c0 = cy * 32;
        int tx = threadIdx.x % 32, ty = threadIdx.x / 32;
        #pragma unroll
        for (int i = ty; i < 32; i += 8)
            tile[i][tx] = x[((size_t)b * 832 + (c0 + i)) * SPA + s0 + tx];
        __syncthreads();
        #pragma unroll
        for (int i = ty; i < 32; i += 8)
            xT[((size_t)b * SPA + (s0 + i)) * 832 + c0 + tx] = __float2half_rn(tile[tx][i]);
    } else {
        int idx = (bid - NT_BLOCKS) * 256 + threadIdx.x;
        if (idx >= jb.start[12]) return;
        int j = 0;
        #pragma unroll
        for (int i = 1; i < 12; i++) if (idx >= jb.start[i]) j = i;
        int local = idx - jb.start[j];
        int ci = jb.cin[j], KT = jb.kt[j];
        if (jb.mode[j] == 0) {
            int c = local / 3, o = local % 3;
            jb.dst[j][local] = jb.src[j][o * ci + c];
        } else {
            int np = jb.npad[j];
            int kp = local / np, n = local % np;
            float v0 = 0.f, v1 = 0.f;
            if (n < jb.cout[j]) {
                int K0 = 2 * kp, K1 = 2 * kp + 1;
                int kk0 = K0 / ci, c0 = K0 - kk0 * ci;
                int kk1 = K1 / ci, c1 = K1 - kk1 * ci;
                v0 = jb.src[j][((size_t)n * ci + c0) * KT + kk0];
                v1 = jb.src[j][((size_t)n * ci + c1) * KT + kk1];
            }
            jb.dst[j][local] = __uint_as_float(h2bits(v0, v1));
        }
    }
}

// ---------------- separable 3-max along one dim, fp16 channels-last -----------
__global__ void k_max3(const __half* __restrict__ in, __half* __restrict__ out,
                       int ddiv, int dmod) {
    size_t idx = (size_t)blockIdx.x * blockDim.x + threadIdx.x;
    if (idx >= (size_t)MTOT * 104) return;
    int c8 = (int)(idx % 104);
    size_t m = idx / 104;
    int s = (int)(m % SPA);
    int coord = (s / ddiv) % dmod;
    const uint4* p = reinterpret_cast<const uint4*>(in) + m * 104 + c8;
    uint4 v = *p;
    if (coord > 0) {
        uint4 u = *(p - (size_t)ddiv * 104);
        v.x = umax2(v.x, u.x); v.y = umax2(v.y, u.y);
        v.z = umax2(v.z, u.z); v.w = umax2(v.w, u.w);
    }
    if (coord < dmod - 1) {
        uint4 u = *(p + (size_t)ddiv * 104);
        v.x = umax2(v.x, u.x); v.y = umax2(v.y, u.y);
        v.z = umax2(v.z, u.z); v.w = umax2(v.w, u.w);
    }
    reinterpret_cast<uint4*>(out)[m * 104 + c8] = v;
}

// ---------------- fp16 tensor GEMM: C[M,Npad] = A[M,K] @ B[K,Npad] ------------
#define ASTG (128 * 20)
#define BSTG (16 * 136)
#define GEMM_SMEM_B ((2 * ASTG + 2 * BSTG) * 4)

__global__ __launch_bounds__(256, 2) void k_gemm_fp16(
    const __half* __restrict__ A, const uint32_t* __restrict__ Bm,
    const float* __restrict__ bias, int nBias,
    float* __restrict__ Cc, int Npad, int Kn)
{
    extern __shared__ uint32_t smu[];
    int tid = threadIdx.x;
    int lane = tid & 31, warp = tid >> 5;
    int warpM = warp & 1, warpN = warp >> 1;
    int m0 = blockIdx.y * 128, n0 = blockIdx.x * 128;
    int g = lane >> 2, tg = lane & 3;

    float acc[4][4][4];
    #pragma unroll
    for (int i = 0; i < 4; i++)
        #pragma unroll
        for (int j = 0; j < 4; j++)
            #pragma unroll
            for (int q = 0; q < 4; q++) acc[i][j][q] = 0.f;

    const int aRow = tid >> 1;
    const __half* aPtr = A + (size_t)(m0 + aRow) * Kn + (tid & 1) * 16;
    uint32_t aBase = (uint32_t)__cvta_generic_to_shared(&smu[aRow * 20 + (tid & 1) * 8]);
    const int bRow = tid >> 4;
    const int bCol = (tid & 15) * 8;
    uint32_t bBase = (uint32_t)__cvta_generic_to_shared(&smu[2 * ASTG + bRow * 136 + bCol]);

    int nChunks = Kn / KC;

    auto issue = [&](int c) {
        int st = c & 1;
        const __half* ap = aPtr + c * KC;
        cpa16(aBase + (uint32_t)st * ASTG * 4,      ap);
        cpa16(aBase + (uint32_t)st * ASTG * 4 + 16, ap + 8);
        const uint32_t* bp = Bm + (size_t)(c * (KC / 2) + bRow) * Npad + n0 + bCol;
        cpa16(bBase + (uint32_t)st * BSTG * 4,      bp);
        cpa16(bBase + (uint32_t)st * BSTG * 4 + 16, bp + 4);
        asm volatile("cp.async.commit_group;");
    };

    issue(0);
    for (int c = 0; c < nChunks; c++) {
        int st = c & 1;
        if (c + 1 < nChunks) {
            issue(c + 1);
            asm volatile("cp.async.wait_group 1;");
        } else {
            asm volatile("cp.async.wait_group 0;");
        }
        __syncthreads();

        const uint32_t* As = smu + (size_t)st * ASTG;
        const uint32_t* Bs = smu + 2 * ASTG + (size_t)st * BSTG;
        #pragma unroll
        for (int ks = 0; ks < 2; ks++) {
            uint32_t af[4][4], bf[4][2];
            #pragma unroll
            for (int mt = 0; mt < 4; mt++) {
                int mr = warpM * 64 + mt * 16 + g;
                af[mt][0] = As[mr * 20       + ks * 8 + tg];
                af[mt][1] = As[(mr + 8) * 20 + ks * 8 + tg];
                af[mt][2] = As[mr * 20       + ks * 8 + 4 + tg];
                af[mt][3] = As[(mr + 8) * 20 + ks * 8 + 4 + tg];
            }
            #pragma unroll
            for (int nt = 0; nt < 4; nt++) {
                int nc = warpN * 32 + nt * 8 + g;
                bf[nt][0] = Bs[(ks * 8 + tg) * 136     + nc];
                bf[nt][1] = Bs[(ks * 8 + 4 + tg) * 136 + nc];
            }
            #pragma unroll
            for (int mt = 0; mt < 4; mt++)
                #pragma unroll
                for (int nt = 0; nt < 4; nt++)
                    asm volatile(
                        "mma.sync.aligned.m16n8k16.row.col.f32.f16.f16.f32 "
                        "{%0,%1,%2,%3}, {%4,%5,%6,%7}, {%8,%9}, {%0,%1,%2,%3};"
                        : "+f"(acc[mt][nt][0]), "+f"(acc[mt][nt][1]),
                          "+f"(acc[mt][nt][2]), "+f"(acc[mt][nt][3])
                        : "r"(af[mt][0]), "r"(af[mt][1]), "r"(af[mt][2]), "r"(af[mt][3]),
                          "r"(bf[nt][0]), "r"(bf[nt][1]));
        }
        __syncthreads();
    }

    #pragma unroll
    for (int mt = 0; mt < 4; mt++) {
        int r0 = m0 + warpM * 64 + mt * 16 + g;
        #pragma unroll
        for (int nt = 0; nt < 4; nt++) {
            int c0 = n0 + warpN * 32 + nt * 8 + tg * 2;
            float b0 = (bias && c0 < nBias) ? bias[c0] : 0.f;
            float b1 = (bias && c0 + 1 < nBias) ? bias[c0 + 1] : 0.f;
            float2 v0 = make_float2(acc[mt][nt][0] + b0, acc[mt][nt][1] + b1);
            float2 v1 = make_float2(acc[mt][nt][2] + b0, acc[mt][nt][3] + b1);
            *reinterpret_cast<float2*>(&Cc[(size_t)r0 * Npad + c0]) = v0;
            *reinterpret_cast<float2*>(&Cc[(size_t)(r0 + 8) * Npad + c0]) = v1;
        }
    }
}

// ---------------- dedicated N=3, K=832 GEMM (fp16 A, fp32 weights/accum) ------
__global__ void k_gemm_n3(const __half* __restrict__ A, const float* __restrict__ Bm,
                          const float* __restrict__ bias, float* __restrict__ out) {
    __shared__ float Bs[832 * 3];
    int tid = threadIdx.x;
    for (int i = tid; i < 832 * 3; i += 256) Bs[i] = Bm[i];
    __syncthreads();
    int warp = tid >> 5, lane = tid & 31;
    int m = blockIdx.x * 8 + warp;
    const uint4* aRow = reinterpret_cast<const uint4*>(A + (size_t)m * 832);
    float s0 = 0.f, s1 = 0.f, s2 = 0.f;
    #pragma unroll
    for (int j = 0; j < 4; j++) {
        int q = lane + j * 32;
        if (q < 104) {
            uint4 v = aRow[q];
            int k = q * 8;
            float2 f0 = h2f(v.x), f1 = h2f(v.y), f2 = h2f(v.z), f3 = h2f(v.w);
            s0 = fmaf(f0.x, Bs[(k+0)*3+0], s0); s1 = fmaf(f0.x, Bs[(k+0)*3+1], s1); s2 = fmaf(f0.x, Bs[(k+0)*3+2], s2);
            s0 = fmaf(f0.y, Bs[(k+1)*3+0], s0); s1 = fmaf(f0.y, Bs[(k+1)*3+1], s1); s2 = fmaf(f0.y, Bs[(k+1)*3+2], s2);
            s0 = fmaf(f1.x, Bs[(k+2)*3+0], s0); s1 = fmaf(f1.x, Bs[(k+2)*3+1], s1); s2 = fmaf(f1.x, Bs[(k+2)*3+2], s2);
            s0 = fmaf(f1.y, Bs[(k+3)*3+0], s0); s1 = fmaf(f1.y, Bs[(k+3)*3+1], s1); s2 = fmaf(f1.y, Bs[(k+3)*3+2], s2);
            s0 = fmaf(f2.x, Bs[(k+4)*3+0], s0); s1 = fmaf(f2.x, Bs[(k+4)*3+1], s1); s2 = fmaf(f2.x, Bs[(k+4)*3+2], s2);
            s0 = fmaf(f2.y, Bs[(k+5)*3+0], s0); s1 = fmaf(f2.y, Bs[(k+5)*3+1], s1); s2 = fmaf(f2.y, Bs[(k+5)*3+2], s2);
            s0 = fmaf(f3.x, Bs[(k+6)*3+0], s0); s1 = fmaf(f3.x, Bs[(k+6)*3+1], s1); s2 = fmaf(f3.x, Bs[(k+6)*3+2], s2);
            s0 = fmaf(f3.y, Bs[(k+7)*3+0], s0); s1 = fmaf(f3.y, Bs[(k+7)*3+1], s1); s2 = fmaf(f3.y, Bs[(k+7)*3+2], s2);
        }
    }
    #pragma unroll
    for (int o = 16; o; o >>= 1) {
        s0 += __shfl_xor_sync(0xffffffffu, s0, o);
        s1 += __shfl_xor_sync(0xffffffffu, s1, o);
        s2 += __shfl_xor_sync(0xffffffffu, s2, o);
    }
    if (lane == 0) {
        out[(size_t)m * 3 + 0] = s0 + bias[0];
        out[(size_t)m * 3 + 1] = s1 + bias[1];
        out[(size_t)m * 3 + 2] = s2 + bias[2];
    }
}

// ---------------- k=1 trilinear sampling (one tap), fp16 src -> fp16 ----------
__global__ void k_sample(const __half* __restrict__ src, const float* __restrict__ off,
                         __half* __restrict__ samp, int C) {
    int m  = blockIdx.x;
    int b = m / SPA, s = m - b * SPA;
    int t = s / (HH * WW); int rem = s - t * HH * WW;
    int h = rem / WW, w = rem - h * WW;
    const float* op = off + (size_t)m * 3;
    float tc = (float)t + op[0];
    float hc = (float)h + op[1];
    float wc = (float)w + op[2];
    float tf = floorf(tc), hf = floorf(hc), wf = floorf(wc);
    float ft = tc - tf, fh = hc - hf, fw = wc - wf;
    int t0 = (int)tf, h0 = (int)hf, w0 = (int)wf;

    float wgt[8]; const uint4* ptr[8];
    #pragma unroll
    for (int ci = 0; ci < 8; ci++) {
        int dt = ci >> 2, dh = (ci >> 1) & 1, dw = ci & 1;
        int ti = t0 + dt, hi = h0 + dh, wi = w0 + dw;
        bool valid = (ti >= 0) && (ti < TT) && (hi >= 0) && (hi < HH) && (wi >= 0) && (wi < WW);
        float wv = (dt ? ft : 1.f - ft) * (dh ? fh : 1.f - fh) * (dw ? fw : 1.f - fw);
        wgt[ci] = valid ? wv : 0.f;
        int tic = min(max(ti, 0), TT - 1);
        int hic = min(max(hi, 0), HH - 1);
        int wic = min(max(wi, 0), WW - 1);
        ptr[ci] = reinterpret_cast<const uint4*>(
            src + ((size_t)b * SPA + (tic * HH + hic) * WW + wic) * C);
    }
    uint4* dst = reinterpret_cast<uint4*>(samp + (size_t)m * C);
    int nC8 = C >> 3;
    for (int c8 = threadIdx.x; c8 < nC8; c8 += blockDim.x) {
        float2 a0 = make_float2(0.f, 0.f), a1 = a0, a2 = a0, a3 = a0;
        #pragma unroll
        for (int ci = 0; ci < 8; ci++) {
            float wv = wgt[ci];
            uint4 v = ptr[ci][c8];
            float2 f0 = h2f(v.x), f1 = h2f(v.y), f2 = h2f(v.z), f3 = h2f(v.w);
            a0.x = fmaf(wv, f0.x, a0.x); a0.y = fmaf(wv, f0.y, a0.y);
            a1.x = fmaf(wv, f1.x, a1.x); a1.y = fmaf(wv, f1.y, a1.y);
            a2.x = fmaf(wv, f2.x, a2.x); a2.y = fmaf(wv, f2.y, a2.y);
            a3.x = fmaf(wv, f3.x, a3.x); a3.y = fmaf(wv, f3.y, a3.y);
        }
        uint4 o;
        o.x = h2bits(a0.x, a0.y); o.y = h2bits(a1.x, a1.y);
        o.z = h2bits(a2.x, a2.y); o.w = h2bits(a3.x, a3.y);
        dst[c8] = o;
    }
}

// ---------------- k=3 trilinear sampling: one CTA per position, fp16 ----------
__global__ void k_sample3(const __half* __restrict__ src, const float* __restrict__ off,
                          __half* __restrict__ samp, int C) {
    __shared__ float sw[27][8];
    __shared__ int   sb[27][8];
    int m = blockIdx.x;
    int b = m / SPA, s = m - b * SPA;
    int t = s / (HH * WW); int rem = s - t * HH * WW;
    int h = rem / WW, w = rem - h * WW;
    int tid = threadIdx.x;
    if (tid < 27) {
        int kt = tid / 9, kh = (tid / 3) % 3, kw = tid % 3;
        const float* op = off + (size_t)m * 128 + tid * 3;
        float tc = (float)(t - 1 + kt) + op[0];
        float hc = (float)(h - 1 + kh) + op[1];
        float wc = (float)(w - 1 + kw) + op[2];
        float tf = floorf(tc), hf = floorf(hc), wf = floorf(wc);
        float ft = tc - tf, fh = hc - hf, fw = wc - wf;
        int t0 = (int)tf, h0 = (int)hf, w0 = (int)wf;
        #pragma unroll
        for (int ci = 0; ci < 8; ci++) {
            int dt = ci >> 2, dh = (ci >> 1) & 1, dw = ci & 1;
            int ti = t0 + dt, hi = h0 + dh, wi = w0 + dw;
            bool valid = (ti >= 0) && (ti < TT) && (hi >= 0) && (hi < HH) && (wi >= 0) && (wi < WW);
            float wv = (dt ? ft : 1.f - ft) * (dh ? fh : 1.f - fh) * (dw ? fw : 1.f - fw);
            sw[tid][ci] = valid ? wv : 0.f;
            int tic = min(max(ti, 0), TT - 1);
            int hic = min(max(hi, 0), HH - 1);
            int wic = min(max(wi, 0), WW - 1);
            sb[tid][ci] = b * SPA + (tic * HH + hic) * WW + wic;
        }
    }
    __syncthreads();
    int nC8 = C >> 3;
    int items = 27 * nC8;
    uint4* dst = reinterpret_cast<uint4*>(samp + (size_t)m * 27 * C);
    for (int it = tid; it < items; it += blockDim.x) {
        int kk = it / nC8, c8 = it - kk * nC8;
        float2 a0 = make_float2(0.f, 0.f), a1 = a0, a2 = a0, a3 = a0;
        #pragma unroll
        for (int ci = 0; ci < 8; ci++) {
            float wv = sw[kk][ci];
            uint4 v = reinterpret_cast<const uint4*>(src + (size_t)sb[kk][ci] * C)[c8];
            float2 f0 = h2f(v.x), f1 = h2f(v.y), f2 = h2f(v.z), f3 = h2f(v.w);
            a0.x = fmaf(wv, f0.x, a0.x); a0.y = fmaf(wv, f0.y, a0.y);
            a1.x = fmaf(wv, f1.x, a1.x); a1.y = fmaf(wv, f1.y, a1.y);
            a2.x = fmaf(wv, f2.x, a2.x); a2.y = fmaf(wv, f2.y, a2.y);
            a3.x = fmaf(wv, f3.x, a3.x); a3.y = fmaf(wv, f3.y, a3.y);
        }
        uint4 o;
        o.x = h2bits(a0.x, a0.y); o.y = h2bits(a1.x, a1.y);
        o.z = h2bits(a2.x, a2.y); o.w = h2bits(a3.x, a3.y);
        dst[(size_t)kk * nC8 + c8] = o;
    }
}

// ---------------- k=3 im2col: one CTA per position, fp16 copy -----------------
__global__ void k_im2col3(const __half* __restrict__ src, __half* __restrict__ outm, int C) {
    __shared__ int sidx[27];
    __shared__ int svalid[27];
    int m = blockIdx.x;
    int b = m / SPA, s = m - b * SPA;
    int t = s / (HH * WW); int rem = s - t * HH * WW;
    int h = rem / WW, w = rem - h * WW;
    int tid = threadIdx.x;
    if (tid < 27) {
        int kt = tid / 9, kh = (tid / 3) % 3, kw = tid % 3;
        int ti = t + kt - 1, hi = h + kh - 1, wi = w + kw - 1;
        bool valid = (ti >= 0) && (ti < TT) && (hi >= 0) && (hi < HH) && (wi >= 0) && (wi < WW);
        svalid[tid] = valid;
        sidx[tid] = b * SPA + (valid ? (ti * HH + hi) * WW + wi : 0);
    }
    __syncthreads();
    int nC8 = C >> 3;
    int items = 27 * nC8;
    uint4* dst = reinterpret_cast<uint4*>(outm + (size_t)m * 27 * C);
    for (int it = tid; it < items; it += blockDim.x) {
        int kk = it / nC8, c8 = it - kk * nC8;
        uint4 v = make_uint4(0u, 0u, 0u, 0u);
        if (svalid[kk])
            v = reinterpret_cast<const uint4*>(src + (size_t)sidx[kk] * C)[c8];
        dst[(size_t)kk * nC8 + c8] = v;
    }
}

// ---------------- per-channel batch stats (mean, biased var) ------------------
__global__ void k_stats(const float* __restrict__ Cm, float* __restrict__ stats,
                        int Nn, int stride) {
    int n = blockIdx.x * 32 + threadIdx.x;
    float s = 0.f, s2 = 0.f;
    if (n < Nn) {
        for (int m = threadIdx.y; m < MTOT; m += 8) {
            float v = Cm[(size_t)m * stride + n];
            s += v; s2 += v * v;
        }
    }
    __shared__ float sh[8][32], sh2[8][32];
    sh[threadIdx.y][threadIdx.x] = s;
    sh2[threadIdx.y][threadIdx.x] = s2;
    __syncthreads();
    if (threadIdx.y == 0 && n < Nn) {
        #pragma unroll
        for (int i = 1; i < 8; i++) { s += sh[i][threadIdx.x]; s2 += sh2[i][threadIdx.x]; }
        float mean = s / (float)MTOT;
        float var  = s2 / (float)MTOT - mean * mean;
        stats[n]       = mean;
        stats[512 + n] = var;
    }
}

// ---------------- BN + ReLU, fp16 channels-last output (intermediates) --------
__global__ void k_bnout_cl(const float* __restrict__ Cm, const float* __restrict__ stats,
                           const float* __restrict__ gamma, const float* __restrict__ beta,
                           __half* __restrict__ outp, int Nn, int stride) {
    size_t idx = (size_t)blockIdx.x * blockDim.x + threadIdx.x;
    size_t tot = (size_t)MTOT * Nn;
    if (idx >= tot) return;
    int n = (int)(idx % Nn);
    size_t m = idx / Nn;
    float sc = gamma[n] * rsqrtf(stats[512 + n] + 1e-5f);
    float v  = fmaf(Cm[m * stride + n] - stats[n], sc, beta[n]);
    outp[idx] = __float2half_rn(fmaxf(v, 0.f));
}

// ---------------- BN + ReLU + tiled transpose into NCDHW concat output --------
__global__ void k_bnout_t(const float* __restrict__ Cm, const float* __restrict__ stats,
                          const float* __restrict__ gamma, const float* __restrict__ beta,
                          float* __restrict__ outp, int stride, int ch0) {
    __shared__ float tile[32][33];
    int b = blockIdx.z, s0 = blockIdx.x * 32, n0 = blockIdx.y * 32;
    int tx = threadIdx.x, ty = threadIdx.y;
    int n = n0 + tx;
    float mean = stats[n];
    float sc = gamma[n] * rsqrtf(stats[512 + n] + 1e-5f);
    float bt = beta[n];
    #pragma unroll
    for (int i = ty; i < 32; i += 8) {
        float v = fmaf(Cm[((size_t)b * SPA + s0 + i) * stride + n] - mean, sc, bt);
        tile[i][tx] = fmaxf(v, 0.f);
    }
    __syncthreads();
    #pragma unroll
    for (int i = ty; i < 32; i += 8)
        outp[((size_t)b * 832 + ch0 + n0 + i) * SPA + s0 + tx] = tile[tx][i];
}

// ============================ host orchestration ==============================
static void run_gemm16(const __half* A, const float* Bm, const float* bias, int nBias,
                       float* C, int Npad, int Kn) {
    static bool attrSet = false;
    if (!attrSet) {
        cudaFuncSetAttribute(k_gemm_fp16, cudaFuncAttributeMaxDynamicSharedMemorySize,
                             GEMM_SMEM_B);
        attrSet = true;
    }
    dim3 grid(Npad / 128, MTOT / 128);
    k_gemm_fp16<<<grid, 256, GEMM_SMEM_B>>>(A, reinterpret_cast<const uint32_t*>(Bm),
                                            bias, nBias, C, Npad, Kn);
}

static void run_bn(const float* conv, float* stats, const float* g, const float* bt,
                   void* outp, int Cout, int stride, int mode, int ch0) {
    k_stats<<<(Cout + 31) / 32, dim3(32, 8)>>>(conv, stats, Cout, stride);
    if (mode == 0) {
        size_t tot = (size_t)MTOT * Cout;
        k_bnout_cl<<<(unsigned)((tot + 255) / 256), 256>>>(conv, stats, g, bt,
                                                           (__half*)outp, Cout, stride);
    } else {
        dim3 grid(SPA / 32, Cout / 32, BB);
        k_bnout_t<<<grid, dim3(32, 8)>>>(conv, stats, g, bt, (float*)outp, stride, ch0);
    }
}

static void run_k1(const __half* srcT, int Cin, int Cout, int Npad,
                   const float* woffT, const float* boffp, const float* wTp,
                   const float* g, const float* bt,
                   float* offb, __half* samp, float* conv, float* stats,
                   void* outp, int mode, int ch0) {
    k_gemm_n3<<<MTOT / 8, 256>>>(srcT, woffT, boffp, offb);   // Cin == 832 always
    k_sample<<<MTOT, 128>>>(srcT, offb, samp, Cin);
    run_gemm16(samp, wTp, nullptr, 0, conv, Npad, Cin);
    run_bn(conv, stats, g, bt, outp, Cout, Npad, mode, ch0);
}

static void run_k3(const __half* srcT, int Cin, int Cout, int Npad,
                   const float* woffT, const float* boffp, const float* wTp,
                   const float* g, const float* bt,
                   float* offb, __half* samp, float* conv, float* stats,
                   void* outp, int mode, int ch0) {
    int Kd = 27 * Cin;
    int blk = (Cin >= 128) ? 256 : 128;
    k_im2col3<<<MTOT, blk>>>(srcT, samp, Cin);
    run_gemm16(samp, woffT, boffp, 81, offb, 128, Kd);   // offsets Npad=128
    k_sample3<<<MTOT, blk>>>(srcT, offb, samp, Cin);
    run_gemm16(samp, wTp, nullptr, 0, conv, Npad, Kd);
    run_bn(conv, stats, g, bt, outp, Cout, Npad, mode, ch0);
}

extern "C" void kernel_launch(void* const* d_in, const int* in_sizes, int n_in,
                              void* d_out, int out_size) {
    const float* x = (const float*)d_in[0];
    const float *woff[6], *boff[6], *wcv[6], *gam[6], *bet[6];
    for (int i = 0; i < 6; i++) {
        woff[i] = (const float*)d_in[1 + 5 * i];
        boff[i] = (const float*)d_in[2 + 5 * i];
        wcv[i]  = (const float*)d_in[3 + 5 * i];
        gam[i]  = (const float*)d_in[4 + 5 * i];
        bet[i]  = (const float*)d_in[5 + 5 * i];
    }
    __half *xT, *xmT, *x1a, *x2a;
    float *sampf, *conv, *offb, *stats, *wT, *woffT;
    cudaGetSymbolAddress((void**)&xT,    g_xT);
    cudaGetSymbolAddress((void**)&xmT,   g_xmT);
    cudaGetSymbolAddress((void**)&x1a,   g_x1a);
    cudaGetSymbolAddress((void**)&x2a,   g_x2a);
    cudaGetSymbolAddress((void**)&sampf, g_samp);
    cudaGetSymbolAddress((void**)&conv,  g_conv);
    cudaGetSymbolAddress((void**)&offb,  g_offb);
    cudaGetSymbolAddress((void**)&stats, g_stats);
    cudaGetSymbolAddress((void**)&wT,    g_wT);
    cudaGetSymbolAddress((void**)&woffT, g_woffT);
    __half* samp = reinterpret_cast<__half*>(sampf);
    float* out = (float*)d_out;

    const int CIN[6]  = {832, 832, 160, 832, 32, 832};
    const int COUT[6] = {256, 160, 320, 32, 128, 128};
    const int NPAD[6] = {256, 256, 384, 128, 128, 128};
    const int KK[6]   = {1, 1, 27, 1, 27, 1};
    size_t wtoff[6], wooff[6];
    {
        size_t a = 0, bsz = 0;
        for (int i = 0; i < 6; i++) {
            wtoff[i] = a;
            a += (size_t)(KK[i] * CIN[i] / 2) * NPAD[i];
        }
        for (int i = 0; i < 6; i++) {
            wooff[i] = bsz;
            bsz += (KK[i] == 1) ? (size_t)CIN[i] * 3
                                : (size_t)(KK[i] * CIN[i] / 2) * 128;
        }
    }

    // launch #1: fused prep (transpose -> fp16 + all 12 weight jobs)
    {
        WJobs jb;
        int pos = 0;
        for (int i = 0; i < 6; i++) {
            jb.src[i] = wcv[i]; jb.dst[i] = wT + wtoff[i];
            jb.cout[i] = COUT[i]; jb.npad[i] = NPAD[i];
            jb.cin[i] = CIN[i]; jb.kt[i] = KK[i]; jb.mode[i] = 1;
            jb.start[i] = pos; pos += (KK[i] * CIN[i] / 2) * NPAD[i];
        }
        for (int i = 0; i < 6; i++) {
            int j = 6 + i;
            jb.src[j] = woff[i]; jb.dst[j] = woffT + wooff[i];
            if (KK[i] == 1) {
                jb.cout[j] = 3; jb.npad[j] = 3; jb.mode[j] = 0;
                jb.cin[j] = CIN[i]; jb.kt[j] = 1;
                jb.start[j] = pos; pos += CIN[i] * 3;
            } else {
                jb.cout[j] = 81; jb.npad[j] = 128; jb.mode[j] = 1;
                jb.cin[j] = CIN[i]; jb.kt[j] = 27;
                jb.start[j] = pos; pos += (27 * CIN[i] / 2) * 128;
            }
        }
        jb.start[12] = pos;
        int wBlocks = (pos + 255) / 256;
        k_prep<<<NT_BLOCKS + wBlocks, 256>>>(jb, x, xT);
    }

    // branch 0
    run_k1(xT, 832, 256, 256, woffT + wooff[0], boff[0], wT + wtoff[0], gam[0], bet[0],
           offb, samp, conv, stats, out, 1, 0);

    // branch 1
    run_k1(xT, 832, 160, 256, woffT + wooff[1], boff[1], wT + wtoff[1], gam[1], bet[1],
           offb, samp, conv, stats, x1a, 0, 0);
    run_k3(x1a, 160, 320, 384, woffT + wooff[2], boff[2], wT + wtoff[2], gam[2], bet[2],
           offb, samp, conv, stats, out, 1, 256);

    // branch 2
    run_k1(xT, 832, 32, 128, woffT + wooff[3], boff[3], wT + wtoff[3], gam[3], bet[3],
           offb, samp, conv, stats, x2a, 0, 0);
    run_k3(x2a, 32, 128, 128, woffT + wooff[4], boff[4], wT + wtoff[4], gam[4], bet[4],
           offb, samp, conv, stats, out, 1, 576);

    // branch 3: separable maxpool (fp16) -> deform k=1
    {
        __half* tmp1 = samp;
        __half* tmp2 = samp + (size_t)MTOT * 832;
        int nthr = (int)(((size_t)MTOT * 104 + 255) / 256);
        k_max3<<<nthr, 256>>>(xT,   tmp1, 1,       WW);
        k_max3<<<nthr, 256>>>(tmp1, tmp2, WW,      HH);
        k_max3<<<nthr, 256>>>(tmp2, xmT,  HH * WW, TT);
    }
    run_k1(xmT, 832, 128, 128, woffT + wooff[5], boff[5], wT + wtoff[5], gam[5], bet[5],
           offb, samp, conv, stats, out, 1, 704);
}